// round 2
// baseline (speedup 1.0000x reference)
#include <cuda_runtime.h>
#include <math.h>

// ---------------- model constants ----------------
#define SEQ    257
#define FZR    6
#define FXA    5
#define L_ZR   (FZR*SEQ)      // 1542
#define L_XA   (FXA*SEQ)      // 1285
#define LTOT   (L_ZR + L_XA)  // 2827
#define DM     512
#define NHEAD  8
#define DH     64
#define HID    2048
#define NBLK   6

static const long SSTRIDE_C = (long)L_ZR * LTOT;   // per-head S stride (cross)
static const long SSTRIDE_S = (long)L_XA * L_XA;   // per-head S stride (self)

// ---------------- scratch (static device memory; no allocs) ----------------
__device__ float g_ACT [LTOT * DM];
__device__ float g_NRM [LTOT * DM];
__device__ float g_QKV [LTOT * 3 * DM];
__device__ float g_ATT [LTOT * DM];
__device__ float g_O   [LTOT * DM];
__device__ float g_B1  [LTOT * DM];
__device__ float g_FF1 [LTOT * 2 * HID];
__device__ float g_H   [LTOT * HID];
__device__ float g_S   [NHEAD * (long)L_ZR * LTOT];
__device__ float g_WQKV[DM * 3 * DM];
__device__ float g_bQKV[3 * DM];
__device__ float g_COND[7 * DM];
__device__ float g_SIL [7 * DM];
__device__ float g_MOD1[7 * 2 * DM];
__device__ float g_MOD2[7 * 2 * DM];
__device__ float g_G1  [7 * DM];
__device__ float g_G2  [7 * DM];

// ---------------- reductions ----------------
__device__ __forceinline__ float blockReduceSum(float v) {
    __shared__ float sh[33];
    int lane = threadIdx.x & 31, w = threadIdx.x >> 5;
    #pragma unroll
    for (int o = 16; o; o >>= 1) v += __shfl_xor_sync(0xffffffffu, v, o);
    if (lane == 0) sh[w] = v;
    __syncthreads();
    if (w == 0) {
        float x = (threadIdx.x < (blockDim.x >> 5)) ? sh[threadIdx.x] : 0.f;
        #pragma unroll
        for (int o = 16; o; o >>= 1) x += __shfl_xor_sync(0xffffffffu, x, o);
        if (lane == 0) sh[32] = x;
    }
    __syncthreads();
    float r = sh[32];
    __syncthreads();
    return r;
}

__device__ __forceinline__ float blockReduceMax(float v) {
    __shared__ float sh[33];
    int lane = threadIdx.x & 31, w = threadIdx.x >> 5;
    #pragma unroll
    for (int o = 16; o; o >>= 1) v = fmaxf(v, __shfl_xor_sync(0xffffffffu, v, o));
    if (lane == 0) sh[w] = v;
    __syncthreads();
    if (w == 0) {
        float x = (threadIdx.x < (blockDim.x >> 5)) ? sh[threadIdx.x] : -1e30f;
        #pragma unroll
        for (int o = 16; o; o >>= 1) x = fmaxf(x, __shfl_xor_sync(0xffffffffu, x, o));
        if (lane == 0) sh[32] = x;
    }
    __syncthreads();
    float r = sh[32];
    __syncthreads();
    return r;
}

__device__ __forceinline__ int cond_of_row(int r) { return (r < L_ZR) ? (r / SEQ) : 6; }

// ---------------- generic fp32 GEMM: C[M,N] = A[M,K]@B[K,N] + bias, opt per-row gate ----------------
// Requirements: N % 64 == 0, K % 16 == 0, lda/ldb multiples of 4, ptrs 16B aligned.
// ep==1: C = (acc + bias) * gate[cond(m)*512 + n]   (only used with N==512)
__global__ __launch_bounds__(256) void sgemm64(
    const float* __restrict__ A, int lda,
    const float* __restrict__ B, int ldb,
    const float* __restrict__ bias,
    float* __restrict__ C, int ldc,
    int M, int N, int K, int ep, const float* __restrict__ gate)
{
    __shared__ float As[16][64];
    __shared__ float Bs[16][64];
    const int tid = threadIdx.x;
    const int tx = tid & 15, ty = tid >> 4;
    const int m0 = blockIdx.y * 64, n0 = blockIdx.x * 64;
    const int ar = tid >> 2, ac = (tid & 3) << 2;
    const int br = tid >> 4, bc = (tid & 15) << 2;
    float acc[4][4] = {};
    for (int k0 = 0; k0 < K; k0 += 16) {
        float4 av = make_float4(0.f, 0.f, 0.f, 0.f);
        int am = m0 + ar;
        if (am < M) av = *(const float4*)(A + (size_t)am * lda + k0 + ac);
        As[ac + 0][ar] = av.x; As[ac + 1][ar] = av.y;
        As[ac + 2][ar] = av.z; As[ac + 3][ar] = av.w;
        float4 bv = *(const float4*)(B + (size_t)(k0 + br) * ldb + n0 + bc);
        *(float4*)&Bs[br][bc] = bv;
        __syncthreads();
        #pragma unroll
        for (int k = 0; k < 16; ++k) {
            float4 a4 = *(const float4*)&As[k][ty << 2];
            float4 b4 = *(const float4*)&Bs[k][tx << 2];
            float a[4] = {a4.x, a4.y, a4.z, a4.w};
            float b[4] = {b4.x, b4.y, b4.z, b4.w};
            #pragma unroll
            for (int i = 0; i < 4; i++)
                #pragma unroll
                for (int j = 0; j < 4; j++)
                    acc[i][j] += a[i] * b[j];
        }
        __syncthreads();
    }
    #pragma unroll
    for (int i = 0; i < 4; i++) {
        int m = m0 + (ty << 2) + i;
        if (m >= M) continue;
        int cidx = cond_of_row(m);
        #pragma unroll
        for (int j = 0; j < 4; j++) {
            int n = n0 + (tx << 2) + j;
            float v = acc[i][j] + bias[n];
            if (ep == 1) v *= gate[cidx * 512 + n];
            C[(size_t)m * ldc + n] = v;
        }
    }
}

// ---------------- attention scores: S[h][m][n] = 0.125 * Q[m,h]·K[n,h] ----------------
__global__ __launch_bounds__(256) void att_scores(
    const float* __restrict__ QKV, float* __restrict__ S,
    int Mq, int qOff, int Nk, int kOff, long Sstride)
{
    const int h = blockIdx.z;
    __shared__ float Qs[64][64];   // [m][k]
    __shared__ float Ks[64][65];   // [n][k], padded
    const int tid = threadIdx.x, tx = tid & 15, ty = tid >> 4;
    const int m0 = blockIdx.y * 64, n0 = blockIdx.x * 64;
    #pragma unroll
    for (int l = 0; l < 4; l++) {
        int v = tid + 256 * l;
        int r = v >> 4, c4 = (v & 15) << 2;
        int qm = m0 + r;
        float4 q4 = make_float4(0.f, 0.f, 0.f, 0.f);
        if (qm < Mq) q4 = *(const float4*)(QKV + (size_t)(qOff + qm) * (3 * DM) + h * 64 + c4);
        *(float4*)&Qs[r][c4] = q4;
        int kn = n0 + r;
        float4 k4 = make_float4(0.f, 0.f, 0.f, 0.f);
        if (kn < Nk) k4 = *(const float4*)(QKV + (size_t)(kOff + kn) * (3 * DM) + DM + h * 64 + c4);
        Ks[r][c4 + 0] = k4.x; Ks[r][c4 + 1] = k4.y;
        Ks[r][c4 + 2] = k4.z; Ks[r][c4 + 3] = k4.w;
    }
    __syncthreads();
    float acc[4][4] = {};
    #pragma unroll 8
    for (int k = 0; k < 64; k++) {
        float a[4], b[4];
        #pragma unroll
        for (int i = 0; i < 4; i++) a[i] = Qs[(ty << 2) + i][k];
        #pragma unroll
        for (int j = 0; j < 4; j++) b[j] = Ks[(tx << 2) + j][k];
        #pragma unroll
        for (int i = 0; i < 4; i++)
            #pragma unroll
            for (int j = 0; j < 4; j++)
                acc[i][j] += a[i] * b[j];
    }
    #pragma unroll
    for (int i = 0; i < 4; i++) {
        int m = m0 + (ty << 2) + i;
        if (m >= Mq) continue;
        #pragma unroll
        for (int j = 0; j < 4; j++) {
            int n = n0 + (tx << 2) + j;
            if (n < Nk) S[(size_t)h * Sstride + (size_t)m * Nk + n] = acc[i][j] * 0.125f;
        }
    }
}

// ---------------- masked softmax over S rows (mask computed analytically) ----------------
__global__ __launch_bounds__(256) void softmax_kernel(
    float* __restrict__ S, long Sstride, int Nk, int isCross)
{
    const int r = blockIdx.x, h = blockIdx.y;
    float* row = S + (size_t)h * Sstride + (size_t)r * Nk;
    const int fq = r / SEQ;
    int a0, a1, b0, b1;
    if (isCross) {
        a0 = fq * SEQ; a1 = a0 + SEQ;
        int j0 = (fq >= 4) ? (fq - 4) : 0;
        b0 = L_ZR + j0 * SEQ; b1 = L_ZR + fq * SEQ;
    } else {
        a0 = 0; a1 = (fq + 1) * SEQ; b0 = 0; b1 = 0;
    }
    float m = -1e30f;
    for (int j = a0 + threadIdx.x; j < a1; j += 256) m = fmaxf(m, row[j]);
    for (int j = b0 + threadIdx.x; j < b1; j += 256) m = fmaxf(m, row[j]);
    m = blockReduceMax(m);
    float s = 0.f;
    for (int j = threadIdx.x; j < Nk; j += 256) {
        bool in = (j >= a0 && j < a1) || (j >= b0 && j < b1);
        float e = in ? expf(row[j] - m) : 0.f;
        row[j] = e; s += e;
    }
    s = blockReduceSum(s);
    float inv = 1.f / s;
    for (int j = threadIdx.x; j < Nk; j += 256) row[j] *= inv;
}

// ---------------- P @ V (per head, N = 64) ----------------
__global__ __launch_bounds__(256) void att_pv(
    const float* __restrict__ S, long Sstride,
    const float* __restrict__ QKV, float* __restrict__ ATT,
    int Mq, int qOff, int Nk, int kOff)
{
    const int h = blockIdx.z;
    __shared__ float Ps[16][64];   // [k][m]
    __shared__ float Vs[16][64];   // [k][n]
    const int tid = threadIdx.x, tx = tid & 15, ty = tid >> 4;
    const int m0 = blockIdx.y * 64;
    const float* Sh = S + (size_t)h * Sstride;
    const int ar = tid >> 2, ac = (tid & 3) << 2;
    const int br = tid >> 4, bc = (tid & 15) << 2;
    float acc[4][4] = {};
    for (int k0 = 0; k0 < Nk; k0 += 16) {
        int m = m0 + ar;
        #pragma unroll
        for (int v = 0; v < 4; v++) {
            int kk = k0 + ac + v;
            Ps[ac + v][ar] = (m < Mq && kk < Nk) ? Sh[(size_t)m * Nk + kk] : 0.f;
        }
        int kb = k0 + br;
        float4 vv = make_float4(0.f, 0.f, 0.f, 0.f);
        if (kb < Nk) vv = *(const float4*)(QKV + (size_t)(kOff + kb) * (3 * DM) + 2 * DM + h * 64 + bc);
        *(float4*)&Vs[br][bc] = vv;
        __syncthreads();
        #pragma unroll
        for (int k = 0; k < 16; k++) {
            float4 a4 = *(const float4*)&Ps[k][ty << 2];
            float4 b4 = *(const float4*)&Vs[k][tx << 2];
            float a[4] = {a4.x, a4.y, a4.z, a4.w};
            float b[4] = {b4.x, b4.y, b4.z, b4.w};
            #pragma unroll
            for (int i = 0; i < 4; i++)
                #pragma unroll
                for (int j = 0; j < 4; j++)
                    acc[i][j] += a[i] * b[j];
        }
        __syncthreads();
    }
    #pragma unroll
    for (int i = 0; i < 4; i++) {
        int m = m0 + (ty << 2) + i;
        if (m >= Mq) continue;
        #pragma unroll
        for (int j = 0; j < 4; j++)
            ATT[(size_t)(qOff + m) * DM + h * 64 + (tx << 2) + j] = acc[i][j];
    }
}

// ---------------- patch/register/action embedding -> g_ACT ----------------
__global__ __launch_bounds__(256) void embed_kernel(
    const float* __restrict__ z, const float* __restrict__ frames,
    const int* __restrict__ actions,
    const float* __restrict__ Wp, const float* __restrict__ bp,
    const float* __restrict__ regs, const float* __restrict__ pe,
    const float* __restrict__ aemb)
{
    const int r = blockIdx.x;
    const bool isZ = (r < L_ZR);
    const int f = isZ ? (r / SEQ) : ((r - L_ZR) / SEQ);
    const int t = isZ ? (r % SEQ) : ((r - L_ZR) % SEQ);
    __shared__ float pv[12];
    if (t < 256 && threadIdx.x < 12) {
        int c = threadIdx.x >> 2, py = (threadIdx.x >> 1) & 1, px = threadIdx.x & 1;
        int ph = t >> 4, pw = t & 15;
        const float* src = isZ ? (z + f * 3072) : (frames + f * 3072);
        pv[threadIdx.x] = src[c * 1024 + (ph * 2 + py) * 32 + (pw * 2 + px)];
    }
    __syncthreads();
    for (int d = threadIdx.x; d < DM; d += 256) {
        float val;
        if (t == 256) {
            val = isZ ? regs[d] : aemb[actions[f] * DM + d];
        } else {
            float s = bp[d] + pe[t * DM + d];
            #pragma unroll
            for (int k = 0; k < 12; k++) s += pv[k] * Wp[k * DM + d];
            val = s;
        }
        g_ACT[(size_t)r * DM + d] = val;
    }
}

// ---------------- cond vectors (7 = 6 noisy + 1 clean), + silu ----------------
__global__ __launch_bounds__(256) void cond_kernel(
    const float* __restrict__ temb, const int* __restrict__ ts)
{
    const int c = blockIdx.x;
    const int row = (c < 6) ? ts[c] : 0;
    for (int d = threadIdx.x; d < DM; d += 256) {
        float v = temb[(size_t)row * DM + d];
        g_COND[c * DM + d] = v;
        g_SIL[c * DM + d] = v / (1.f + expf(-v));
    }
}

// ---------------- concat Wq|Wk|Wv into one [512,1536] matrix ----------------
__global__ __launch_bounds__(256) void wqkv_kernel(
    const float* __restrict__ Wq, const float* __restrict__ Wk, const float* __restrict__ Wv,
    const float* __restrict__ bq, const float* __restrict__ bk, const float* __restrict__ bv)
{
    int idx = blockIdx.x * 256 + threadIdx.x;      // 512*1536 total
    int k = idx / 1536, n = idx % 1536;
    int sel = n >> 9, col = n & 511;
    const float* Ws = (sel == 0) ? Wq : (sel == 1) ? Wk : Wv;
    g_WQKV[idx] = Ws[k * DM + col];
    if (k == 0) {
        const float* bs = (sel == 0) ? bq : (sel == 1) ? bk : bv;
        g_bQKV[n] = bs[col];
    }
}

// ---------------- LN + AdaLN modulation: Y = LN(X)*(1+scale[c]) + shift[c] ----------------
__global__ __launch_bounds__(256) void lnmod_kernel(
    const float* __restrict__ X, const float* __restrict__ MOD, float* __restrict__ Y)
{
    const int r = blockIdx.x;
    const int cidx = cond_of_row(r);
    const size_t base = (size_t)r * DM;
    const int d0 = threadIdx.x, d1 = threadIdx.x + 256;
    float v0 = X[base + d0], v1 = X[base + d1];
    float mu = blockReduceSum(v0 + v1) * (1.f / 512.f);
    float c0 = v0 - mu, c1 = v1 - mu;
    float var = blockReduceSum(c0 * c0 + c1 * c1) * (1.f / 512.f);
    float inv = rsqrtf(var + 1e-5f);
    const float* sc = MOD + cidx * 1024;
    Y[base + d0] = c0 * inv * (1.f + sc[d0]) + sc[512 + d0];
    Y[base + d1] = c1 * inv * (1.f + sc[d1]) + sc[512 + d1];
}

// ---------------- gate1 * NRM + attn_out, then LN + mod2 -> B1 ----------------
__global__ __launch_bounds__(256) void gatereslnmod_kernel(
    const float* __restrict__ NRM, const float* __restrict__ O,
    const float* __restrict__ G, const float* __restrict__ MOD, float* __restrict__ Y)
{
    const int r = blockIdx.x;
    const int cidx = cond_of_row(r);
    const size_t base = (size_t)r * DM;
    const int d0 = threadIdx.x, d1 = threadIdx.x + 256;
    float u0 = NRM[base + d0] * G[cidx * 512 + d0] + O[base + d0];
    float u1 = NRM[base + d1] * G[cidx * 512 + d1] + O[base + d1];
    float mu = blockReduceSum(u0 + u1) * (1.f / 512.f);
    float c0 = u0 - mu, c1 = u1 - mu;
    float var = blockReduceSum(c0 * c0 + c1 * c1) * (1.f / 512.f);
    float inv = rsqrtf(var + 1e-5f);
    const float* sc = MOD + cidx * 1024;
    Y[base + d0] = c0 * inv * (1.f + sc[d0]) + sc[512 + d0];
    Y[base + d1] = c1 * inv * (1.f + sc[d1]) + sc[512 + d1];
}

// ---------------- GEGLU elementwise: H = a * gelu_exact(g) ----------------
__global__ __launch_bounds__(256) void geglu_kernel()
{
    int idx = blockIdx.x * 256 + threadIdx.x;
    if (idx >= LTOT * HID) return;
    int r = idx / HID, c = idx % HID;
    float a = g_FF1[(size_t)r * (2 * HID) + c];
    float g = g_FF1[(size_t)r * (2 * HID) + HID + c];
    g_H[idx] = a * 0.5f * g * (1.f + erff(g * 0.70710678118654752f));
}

// ---------------- unpatch: out[f,c,h,w] = zr_token . W_unpatch + b ----------------
__global__ __launch_bounds__(256) void unpatch_kernel(
    const float* __restrict__ Wu, const float* __restrict__ bu, float* __restrict__ out)
{
    int idx = blockIdx.x * 256 + threadIdx.x;   // 6*256*12 = 18432
    if (idx >= FZR * 256 * 12) return;
    int j = idx % 12, tl = idx / 12;
    int f = tl >> 8, t = tl & 255;
    const float* a = g_ACT + (size_t)(f * SEQ + t) * DM;
    float s = bu[j];
    #pragma unroll 4
    for (int d = 0; d < DM; d++) s += a[d] * Wu[d * 12 + j];
    int c = j >> 2, py = (j >> 1) & 1, px = j & 1;
    int ph = t >> 4, pw = t & 15;
    out[f * 3072 + c * 1024 + (ph * 2 + py) * 32 + (pw * 2 + px)] = s;
}

// ---------------- host orchestration ----------------
extern "C" void kernel_launch(void* const* d_in, const int* in_sizes, int n_in,
                              void* d_out, int out_size)
{
    const float* z      = (const float*)d_in[0];
    const float* frames = (const float*)d_in[1];
    const int*   actions= (const int*)  d_in[2];
    const int*   ts     = (const int*)  d_in[3];
    const float* Wp     = (const float*)d_in[4];
    const float* bp     = (const float*)d_in[5];
    const float* Wu     = (const float*)d_in[6];
    const float* bu     = (const float*)d_in[7];
    const float* regs   = (const float*)d_in[8];
    const float* pe     = (const float*)d_in[9];
    const float* aemb   = (const float*)d_in[10];
    const float* temb   = (const float*)d_in[11];
    const float* Wm1    = (const float*)d_in[12];
    const float* bm1    = (const float*)d_in[13];
    const float* Wm2    = (const float*)d_in[14];
    const float* bm2    = (const float*)d_in[15];
    const float* Wq     = (const float*)d_in[16];
    const float* bq     = (const float*)d_in[17];
    const float* Wk     = (const float*)d_in[18];
    const float* bk     = (const float*)d_in[19];
    const float* Wv     = (const float*)d_in[20];
    const float* bv     = (const float*)d_in[21];
    const float* Wo     = (const float*)d_in[22];
    const float* bo     = (const float*)d_in[23];
    const float* Wg1    = (const float*)d_in[24];
    const float* bg1    = (const float*)d_in[25];
    const float* Wg2    = (const float*)d_in[26];
    const float* bg2    = (const float*)d_in[27];
    const float* Wge    = (const float*)d_in[28];
    const float* bge    = (const float*)d_in[29];
    const float* Wff    = (const float*)d_in[30];
    const float* bff    = (const float*)d_in[31];

    float *ACT, *NRM, *QKV, *ATT, *O, *B1, *FF1, *H, *S, *WQKVp, *bQKVp;
    float *COND, *SIL, *MOD1, *MOD2, *G1, *G2;
    cudaGetSymbolAddress((void**)&ACT,  g_ACT);
    cudaGetSymbolAddress((void**)&NRM,  g_NRM);
    cudaGetSymbolAddress((void**)&QKV,  g_QKV);
    cudaGetSymbolAddress((void**)&ATT,  g_ATT);
    cudaGetSymbolAddress((void**)&O,    g_O);
    cudaGetSymbolAddress((void**)&B1,   g_B1);
    cudaGetSymbolAddress((void**)&FF1,  g_FF1);
    cudaGetSymbolAddress((void**)&H,    g_H);
    cudaGetSymbolAddress((void**)&S,    g_S);
    cudaGetSymbolAddress((void**)&WQKVp,g_WQKV);
    cudaGetSymbolAddress((void**)&bQKVp,g_bQKV);
    cudaGetSymbolAddress((void**)&COND, g_COND);
    cudaGetSymbolAddress((void**)&SIL,  g_SIL);
    cudaGetSymbolAddress((void**)&MOD1, g_MOD1);
    cudaGetSymbolAddress((void**)&MOD2, g_MOD2);
    cudaGetSymbolAddress((void**)&G1,   g_G1);
    cudaGetSymbolAddress((void**)&G2,   g_G2);

    const int MT = (LTOT + 63) / 64;      // 45 row tiles over all tokens
    const int MTC = (L_ZR + 63) / 64;     // 25 (cross queries)
    const int MTS = (L_XA + 63) / 64;     // 21 (self queries)
    const int NTC = (LTOT + 63) / 64;     // 45 (cross keys)
    const int NTS = (L_XA + 63) / 64;     // 21 (self keys)

    embed_kernel<<<LTOT, 256>>>(z, frames, actions, Wp, bp, regs, pe, aemb);
    cond_kernel<<<7, 256>>>(temb, ts);

    for (int i = 0; i < NBLK; i++) {
        const float* Wm1i = Wm1 + (size_t)i * DM * 2 * DM;
        const float* bm1i = bm1 + (size_t)i * 2 * DM;
        const float* Wm2i = Wm2 + (size_t)i * DM * 2 * DM;
        const float* bm2i = bm2 + (size_t)i * 2 * DM;
        const float* Wqi  = Wq  + (size_t)i * DM * DM;
        const float* bqi  = bq  + (size_t)i * DM;
        const float* Wki  = Wk  + (size_t)i * DM * DM;
        const float* bki  = bk  + (size_t)i * DM;
        const float* Wvi  = Wv  + (size_t)i * DM * DM;
        const float* bvi  = bv  + (size_t)i * DM;
        const float* Woi  = Wo  + (size_t)i * DM * DM;
        const float* boi  = bo  + (size_t)i * DM;
        const float* Wg1i = Wg1 + (size_t)i * DM * DM;
        const float* bg1i = bg1 + (size_t)i * DM;
        const float* Wg2i = Wg2 + (size_t)i * DM * DM;
        const float* bg2i = bg2 + (size_t)i * DM;
        const float* Wgei = Wge + (size_t)i * DM * 2 * HID;
        const float* bgei = bge + (size_t)i * 2 * HID;
        const float* Wffi = Wff + (size_t)i * HID * DM;
        const float* bffi = bff + (size_t)i * DM;

        // per-frame AdaLN / gate vectors (7 conds)
        sgemm64<<<dim3(16, 1), 256>>>(SIL, DM, Wm1i, 2 * DM, bm1i, MOD1, 2 * DM, 7, 2 * DM, DM, 0, nullptr);
        sgemm64<<<dim3(16, 1), 256>>>(SIL, DM, Wm2i, 2 * DM, bm2i, MOD2, 2 * DM, 7, 2 * DM, DM, 0, nullptr);
        sgemm64<<<dim3(8, 1),  256>>>(COND, DM, Wg1i, DM, bg1i, G1, DM, 7, DM, DM, 0, nullptr);
        sgemm64<<<dim3(8, 1),  256>>>(COND, DM, Wg2i, DM, bg2i, G2, DM, 7, DM, DM, 0, nullptr);

        // LN + mod1 on both streams
        lnmod_kernel<<<LTOT, 256>>>(ACT, MOD1, NRM);

        // QKV (shared by cross + self, since xkv = [zrn; xan])
        wqkv_kernel<<<(DM * 3 * DM) / 256, 256>>>(Wqi, Wki, Wvi, bqi, bki, bvi);
        sgemm64<<<dim3(24, MT), 256>>>(NRM, DM, WQKVp, 3 * DM, bQKVp, QKV, 3 * DM, LTOT, 3 * DM, DM, 0, nullptr);

        // cross attention: q = zr rows, kv = all rows
        att_scores<<<dim3(NTC, MTC, NHEAD), 256>>>(QKV, S, L_ZR, 0, LTOT, 0, SSTRIDE_C);
        softmax_kernel<<<dim3(L_ZR, NHEAD), 256>>>(S, SSTRIDE_C, LTOT, 1);
        att_pv<<<dim3(1, MTC, NHEAD), 256>>>(S, SSTRIDE_C, QKV, ATT, L_ZR, 0, LTOT, 0);

        // self attention: q = kv = xa rows
        att_scores<<<dim3(NTS, MTS, NHEAD), 256>>>(QKV, S, L_XA, L_ZR, L_XA, L_ZR, SSTRIDE_S);
        softmax_kernel<<<dim3(L_XA, NHEAD), 256>>>(S, SSTRIDE_S, L_XA, 0);
        att_pv<<<dim3(1, MTS, NHEAD), 256>>>(S, SSTRIDE_S, QKV, ATT, L_XA, L_ZR, L_XA, L_ZR);

        // output projection
        sgemm64<<<dim3(8, MT), 256>>>(ATT, DM, Woi, DM, boi, O, DM, LTOT, DM, DM, 0, nullptr);

        // gate1*NRM + attn, LN + mod2
        gatereslnmod_kernel<<<LTOT, 256>>>(NRM, O, G1, MOD2, B1);

        // GEGLU FFN, fused gate2 in ffout epilogue -> new ACT
        sgemm64<<<dim3(64, MT), 256>>>(B1, DM, Wgei, 2 * HID, bgei, FF1, 2 * HID, LTOT, 2 * HID, DM, 0, nullptr);
        geglu_kernel<<<(LTOT * HID + 255) / 256, 256>>>();
        sgemm64<<<dim3(8, MT), 256>>>(H, HID, Wffi, DM, bffi, ACT, DM, LTOT, DM, HID, 1, G2);
    }

    unpatch_kernel<<<(FZR * 256 * 12 + 255) / 256, 256>>>(Wu, bu, (float*)d_out);
}